// round 9
// baseline (speedup 1.0000x reference)
#include <cuda_runtime.h>
#include <cuda_fp16.h>
#include <cstdint>

#define Bv 8
#define Tv 512
#define Mv 16
#define Dv 128
#define Pv 256
#define Hv 8
#define Ev 32
#define ROWS (Bv*Tv*Mv)   // 65536
#define MP 4096           // Mv*Pv: element stride between consecutive t

// Projected Q,K,V stored as fp16 hi/lo pairs (split done in GEMM epilogue).
// Q is pre-scaled by 1/sqrt(E). Layout: ((b*T+t)*M+m)*P + h*E + e
__device__ half g_qh[(size_t)ROWS * Pv];
__device__ half g_ql[(size_t)ROWS * Pv];
__device__ half g_kh[(size_t)ROWS * Pv];
__device__ half g_kl[(size_t)ROWS * Pv];
__device__ half g_vh[(size_t)ROWS * Pv];
__device__ half g_vl[(size_t)ROWS * Pv];

__device__ __forceinline__ void split2(float x, half& hi, half& lo) {
    hi = __float2half_rn(x);
    lo = __float2half_rn(x - __half2float(hi));
}
__device__ __forceinline__ void splitpack(float x, float y, uint32_t& hi, uint32_t& lo) {
    half hx, lx, hy, ly;
    split2(x, hx, lx);
    split2(y, hy, ly);
    __half2 h = __halves2half2(hx, hy);
    __half2 l = __halves2half2(lx, ly);
    hi = *(uint32_t*)&h;
    lo = *(uint32_t*)&l;
}
// D = A(16x16 f16, row) @ B(16x8 f16, col) + D (f32)
__device__ __forceinline__ void mma16816(float* c, const uint32_t* a, const uint32_t* b) {
    asm volatile(
        "mma.sync.aligned.m16n8k16.row.col.f32.f16.f16.f32 "
        "{%0,%1,%2,%3}, {%4,%5,%6,%7}, {%8,%9}, {%0,%1,%2,%3};\n"
        : "+f"(c[0]), "+f"(c[1]), "+f"(c[2]), "+f"(c[3])
        : "r"(a[0]), "r"(a[1]), "r"(a[2]), "r"(a[3]), "r"(b[0]), "r"(b[1]));
}

// ===========================================================================
// QKV GEMM via mma.m16n8k16 with fp16 hi/lo 3-term splits.
// Epilogue writes hi/lo half arrays (Q pre-scaled) for the attention stage.
// ===========================================================================
#define GLD 72
#define GEMM_SMEM (4 * 128 * GLD * 2)             // 73728 bytes

__global__ __launch_bounds__(256) void qkv_gemm_mma(
    const float* __restrict__ A,
    const float* __restrict__ Wq, const float* __restrict__ bq,
    const float* __restrict__ Wk, const float* __restrict__ bk,
    const float* __restrict__ Wv, const float* __restrict__ bv)
{
    extern __shared__ half sm[];
    half* Ahi = sm;                 // [128][GLD]
    half* Alo = Ahi + 128 * GLD;
    half* Bhi = Alo + 128 * GLD;    // [c][k]
    half* Blo = Bhi + 128 * GLD;

    const int which = blockIdx.z;
    const float* __restrict__ W    = (which == 0) ? Wq : (which == 1) ? Wk : Wv;
    const float* __restrict__ bias = (which == 0) ? bq : (which == 1) ? bk : bv;
    half* __restrict__ Chi         = (which == 0) ? g_qh : (which == 1) ? g_kh : g_vh;
    half* __restrict__ Clo         = (which == 0) ? g_ql : (which == 1) ? g_kl : g_vl;
    const float oscale = (which == 0) ? 0.17677669529663687f : 1.0f;  // 1/sqrt(32) folded into Q

    const int tid  = threadIdx.x;
    const int w    = tid >> 5;
    const int lane = tid & 31;
    const int g    = lane >> 2;
    const int c2   = (lane & 3) * 2;
    const int rowBase = blockIdx.x * 128;
    const int colBase = blockIdx.y * 128;

    float acc[16][4];
    #pragma unroll
    for (int nb = 0; nb < 16; nb++)
        acc[nb][0] = acc[nb][1] = acc[nb][2] = acc[nb][3] = 0.f;

    for (int kk = 0; kk < Dv; kk += 64) {
        __syncthreads();
        for (int i = tid; i < 128 * 16; i += 256) {
            int r = i >> 4, k4 = (i & 15) * 4;
            float4 a = *(const float4*)&A[(size_t)(rowBase + r) * Dv + kk + k4];
            uint32_t h0, l0, h1, l1;
            splitpack(a.x, a.y, h0, l0);
            splitpack(a.z, a.w, h1, l1);
            *(uint32_t*)&Ahi[r * GLD + k4]     = h0;
            *(uint32_t*)&Ahi[r * GLD + k4 + 2] = h1;
            *(uint32_t*)&Alo[r * GLD + k4]     = l0;
            *(uint32_t*)&Alo[r * GLD + k4 + 2] = l1;
        }
        for (int i = tid; i < 128 * 16; i += 256) {
            int c = i >> 4, k4 = (i & 15) * 4;
            float w0 = W[(size_t)(kk + k4 + 0) * Pv + colBase + c];
            float w1 = W[(size_t)(kk + k4 + 1) * Pv + colBase + c];
            float w2 = W[(size_t)(kk + k4 + 2) * Pv + colBase + c];
            float w3 = W[(size_t)(kk + k4 + 3) * Pv + colBase + c];
            uint32_t h0, l0, h1, l1;
            splitpack(w0, w1, h0, l0);
            splitpack(w2, w3, h1, l1);
            *(uint32_t*)&Bhi[c * GLD + k4]     = h0;
            *(uint32_t*)&Bhi[c * GLD + k4 + 2] = h1;
            *(uint32_t*)&Blo[c * GLD + k4]     = l0;
            *(uint32_t*)&Blo[c * GLD + k4 + 2] = l1;
        }
        __syncthreads();

        #pragma unroll
        for (int ks = 0; ks < 4; ks++) {
            uint32_t ah[4], al[4];
            const half* a0 = &Ahi[(w * 16 + g) * GLD + ks * 16 + c2];
            const half* a1 = a0 + 8 * GLD;
            ah[0] = *(const uint32_t*)a0;
            ah[1] = *(const uint32_t*)a1;
            ah[2] = *(const uint32_t*)(a0 + 8);
            ah[3] = *(const uint32_t*)(a1 + 8);
            const half* b0 = &Alo[(w * 16 + g) * GLD + ks * 16 + c2];
            const half* b1 = b0 + 8 * GLD;
            al[0] = *(const uint32_t*)b0;
            al[1] = *(const uint32_t*)b1;
            al[2] = *(const uint32_t*)(b0 + 8);
            al[3] = *(const uint32_t*)(b1 + 8);

            #pragma unroll
            for (int nb = 0; nb < 16; nb++) {
                uint32_t bh[2], bl[2];
                const half* bp = &Bhi[(nb * 8 + g) * GLD + ks * 16 + c2];
                bh[0] = *(const uint32_t*)bp;
                bh[1] = *(const uint32_t*)(bp + 8);
                const half* lp = &Blo[(nb * 8 + g) * GLD + ks * 16 + c2];
                bl[0] = *(const uint32_t*)lp;
                bl[1] = *(const uint32_t*)(lp + 8);
                mma16816(acc[nb], ah, bh);
                mma16816(acc[nb], ah, bl);
                mma16816(acc[nb], al, bh);
            }
        }
    }

    const int r0 = rowBase + w * 16 + g;
    const int r1 = r0 + 8;
    #pragma unroll
    for (int nb = 0; nb < 16; nb++) {
        int col = colBase + nb * 8 + c2;
        float bx = __ldg(&bias[col]);
        float by = __ldg(&bias[col + 1]);
        float v00 = (acc[nb][0] + bx) * oscale, v01 = (acc[nb][1] + by) * oscale;
        float v10 = (acc[nb][2] + bx) * oscale, v11 = (acc[nb][3] + by) * oscale;
        uint32_t h0, l0, h1, l1;
        splitpack(v00, v01, h0, l0);
        splitpack(v10, v11, h1, l1);
        *(uint32_t*)&Chi[(size_t)r0 * Pv + col] = h0;
        *(uint32_t*)&Clo[(size_t)r0 * Pv + col] = l0;
        *(uint32_t*)&Chi[(size_t)r1 * Pv + col] = h1;
        *(uint32_t*)&Clo[(size_t)r1 * Pv + col] = l1;
    }
}

// ---------------------------------------------------------------------------
// Flash attention, mma.m16n8k16. Q/K/V arrive pre-split (hi/lo half) — no cvt
// in the staging path; only P needs splitting per tile.
// ---------------------------------------------------------------------------
__global__ __launch_bounds__(256) void attn_mma(
    const int* __restrict__ mask, float* __restrict__ out)
{
    __shared__ half Khi[64][40];
    __shared__ half Klo[64][40];
    __shared__ half Vthi[32][72];
    __shared__ half Vtlo[32][72];
    __shared__ float msk[64];

    const int tid  = threadIdx.x;
    const int w    = tid >> 5;
    const int lane = tid & 31;
    const int g    = lane >> 2;
    const int c2   = (lane & 3) * 2;
    const int qt   = blockIdx.x;
    const int bmh  = blockIdx.y;
    const int h  = bmh & (Hv - 1);
    const int m_ = (bmh >> 3) & (Mv - 1);
    const int b  = bmh >> 7;

    const size_t base = ((size_t)b * Tv * Mv + m_) * (size_t)Pv + (size_t)h * Ev;
    const int qrow = qt * 128 + w * 16 + g;

    // ---- Q fragments: direct half2 loads (scale already folded) ----
    uint32_t qh[2][4], ql[2][4];
    {
        const size_t o0 = base + (size_t)qrow * MP;
        const size_t o1 = o0 + (size_t)8 * MP;
        #pragma unroll
        for (int ks = 0; ks < 2; ks++) {
            int c = ks * 16 + c2;
            qh[ks][0] = *(const uint32_t*)&g_qh[o0 + c];
            qh[ks][1] = *(const uint32_t*)&g_qh[o1 + c];
            qh[ks][2] = *(const uint32_t*)&g_qh[o0 + c + 8];
            qh[ks][3] = *(const uint32_t*)&g_qh[o1 + c + 8];
            ql[ks][0] = *(const uint32_t*)&g_ql[o0 + c];
            ql[ks][1] = *(const uint32_t*)&g_ql[o1 + c];
            ql[ks][2] = *(const uint32_t*)&g_ql[o0 + c + 8];
            ql[ks][3] = *(const uint32_t*)&g_ql[o1 + c + 8];
        }
    }

    float O[4][4] = {};
    float mrow0 = -1e30f, mrow1 = -1e30f;
    float lrow0 = 0.f,    lrow1 = 0.f;

    for (int kt = 0; kt < 8; kt++) {
        __syncthreads();
        // stage 64 keys: pure half moves, vectorized 4-half loads
        for (int i = tid; i < 64 * 8; i += 256) {
            int row = i >> 3, e4 = (i & 7) * 4;
            size_t off = base + (size_t)(kt * 64 + row) * MP + e4;
            uint2 kh2 = *(const uint2*)&g_kh[off];
            uint2 kl2 = *(const uint2*)&g_kl[off];
            *(uint2*)&Khi[row][e4] = kh2;
            *(uint2*)&Klo[row][e4] = kl2;
            uint2 vh2 = *(const uint2*)&g_vh[off];
            uint2 vl2 = *(const uint2*)&g_vl[off];
            const half* vh4 = (const half*)&vh2;
            const half* vl4 = (const half*)&vl2;
            #pragma unroll
            for (int jj = 0; jj < 4; jj++) {
                Vthi[e4 + jj][row] = vh4[jj];
                Vtlo[e4 + jj][row] = vl4[jj];
            }
        }
        if (tid < 64)
            msk[tid] = mask[(size_t)(b * Tv + kt * 64 + tid) * Mv + m_] ? 1.f : 0.f;
        __syncthreads();

        // ---- S = Qs @ K^T ----
        float S[8][4];
        #pragma unroll
        for (int nb = 0; nb < 8; nb++) {
            S[nb][0] = S[nb][1] = S[nb][2] = S[nb][3] = 0.f;
            #pragma unroll
            for (int ks = 0; ks < 2; ks++) {
                uint32_t bh[2], bl[2];
                const half* kp = &Khi[nb * 8 + g][ks * 16 + c2];
                bh[0] = *(const uint32_t*)kp;  bh[1] = *(const uint32_t*)(kp + 8);
                const half* lp = &Klo[nb * 8 + g][ks * 16 + c2];
                bl[0] = *(const uint32_t*)lp;  bl[1] = *(const uint32_t*)(lp + 8);
                mma16816(S[nb], qh[ks], bh);
                mma16816(S[nb], qh[ks], bl);
                mma16816(S[nb], ql[ks], bh);
            }
        }

        // ---- mask + online softmax ----
        float mt0 = -1e30f, mt1 = -1e30f;
        #pragma unroll
        for (int nb = 0; nb < 8; nb++) {
            float mk0 = msk[nb * 8 + c2];
            float mk1 = msk[nb * 8 + c2 + 1];
            S[nb][0] = (mk0 != 0.f) ? S[nb][0] : -1e30f;
            S[nb][1] = (mk1 != 0.f) ? S[nb][1] : -1e30f;
            S[nb][2] = (mk0 != 0.f) ? S[nb][2] : -1e30f;
            S[nb][3] = (mk1 != 0.f) ? S[nb][3] : -1e30f;
            mt0 = fmaxf(mt0, fmaxf(S[nb][0], S[nb][1]));
            mt1 = fmaxf(mt1, fmaxf(S[nb][2], S[nb][3]));
        }
        mt0 = fmaxf(mt0, __shfl_xor_sync(0xffffffffu, mt0, 1));
        mt0 = fmaxf(mt0, __shfl_xor_sync(0xffffffffu, mt0, 2));
        mt1 = fmaxf(mt1, __shfl_xor_sync(0xffffffffu, mt1, 1));
        mt1 = fmaxf(mt1, __shfl_xor_sync(0xffffffffu, mt1, 2));

        float mn0 = fmaxf(mrow0, mt0), mn1 = fmaxf(mrow1, mt1);
        float a0 = __expf(mrow0 - mn0), a1 = __expf(mrow1 - mn1);
        mrow0 = mn0; mrow1 = mn1;

        float rs0 = 0.f, rs1 = 0.f;
        #pragma unroll
        for (int nb = 0; nb < 8; nb++) {
            S[nb][0] = __expf(S[nb][0] - mn0);
            S[nb][1] = __expf(S[nb][1] - mn0);
            S[nb][2] = __expf(S[nb][2] - mn1);
            S[nb][3] = __expf(S[nb][3] - mn1);
            rs0 += S[nb][0] + S[nb][1];
            rs1 += S[nb][2] + S[nb][3];
        }
        rs0 += __shfl_xor_sync(0xffffffffu, rs0, 1);
        rs0 += __shfl_xor_sync(0xffffffffu, rs0, 2);
        rs1 += __shfl_xor_sync(0xffffffffu, rs1, 1);
        rs1 += __shfl_xor_sync(0xffffffffu, rs1, 2);
        lrow0 = lrow0 * a0 + rs0;
        lrow1 = lrow1 * a1 + rs1;
        #pragma unroll
        for (int eb = 0; eb < 4; eb++) {
            O[eb][0] *= a0; O[eb][1] *= a0;
            O[eb][2] *= a1; O[eb][3] *= a1;
        }

        // ---- O += P @ V ----
        #pragma unroll
        for (int kb = 0; kb < 4; kb++) {
            uint32_t ph[4], pl[4];
            splitpack(S[2 * kb][0],     S[2 * kb][1],     ph[0], pl[0]);
            splitpack(S[2 * kb][2],     S[2 * kb][3],     ph[1], pl[1]);
            splitpack(S[2 * kb + 1][0], S[2 * kb + 1][1], ph[2], pl[2]);
            splitpack(S[2 * kb + 1][2], S[2 * kb + 1][3], ph[3], pl[3]);
            #pragma unroll
            for (int eb = 0; eb < 4; eb++) {
                uint32_t vh[2], vl[2];
                const half* vp = &Vthi[eb * 8 + g][kb * 16 + c2];
                vh[0] = *(const uint32_t*)vp;  vh[1] = *(const uint32_t*)(vp + 8);
                const half* vq = &Vtlo[eb * 8 + g][kb * 16 + c2];
                vl[0] = *(const uint32_t*)vq;  vl[1] = *(const uint32_t*)(vq + 8);
                mma16816(O[eb], ph, vh);
                mma16816(O[eb], ph, vl);
                mma16816(O[eb], pl, vh);
            }
        }
    }

    float inv0 = (mrow0 > -1e29f) ? (1.f / lrow0) : 0.f;
    float inv1 = (mrow1 > -1e29f) ? (1.f / lrow1) : 0.f;
    float* o0 = &out[base + (size_t)qrow * MP];
    float* o1 = o0 + (size_t)8 * MP;
    #pragma unroll
    for (int eb = 0; eb < 4; eb++) {
        int e = eb * 8 + c2;
        o0[e]     = O[eb][0] * inv0;
        o0[e + 1] = O[eb][1] * inv0;
        o1[e]     = O[eb][2] * inv1;
        o1[e + 1] = O[eb][3] * inv1;
    }
}

// ---------------------------------------------------------------------------
// Inputs (metadata order): inp, mask, Wq, bq, Wk, bk, Wv, bv
// ---------------------------------------------------------------------------
extern "C" void kernel_launch(void* const* d_in, const int* in_sizes, int n_in,
                              void* d_out, int out_size)
{
    (void)in_sizes; (void)n_in; (void)out_size;
    const float* inp  = (const float*)d_in[0];
    const int*   mask = (const int*)d_in[1];
    const float* Wq = (const float*)d_in[2];
    const float* bq = (const float*)d_in[3];
    const float* Wk = (const float*)d_in[4];
    const float* bk = (const float*)d_in[5];
    const float* Wv = (const float*)d_in[6];
    const float* bv = (const float*)d_in[7];
    float* out = (float*)d_out;

    static bool attr_done = false;
    if (!attr_done) {
        cudaFuncSetAttribute(qkv_gemm_mma, cudaFuncAttributeMaxDynamicSharedMemorySize, GEMM_SMEM);
        attr_done = true;
    }

    dim3 ggrid(ROWS / 128, Pv / 128, 3);   // (512, 2, 3)
    qkv_gemm_mma<<<ggrid, 256, GEMM_SMEM>>>(inp, Wq, bq, Wk, bk, Wv, bv);

    dim3 agrid(Tv / 128, Bv * Mv * Hv);    // (4, 1024)
    attn_mma<<<agrid, 256>>>(mask, out);
}